// round 16
// baseline (speedup 1.0000x reference)
#include <cuda_runtime.h>
#include <cuda_bf16.h>

#define B_ROWS          131072
#define XSTRIDE         512                       // S*D floats per batch row
#define THREADS         128
#define ROWS_PER_BLOCK  128
#define NBLK            (B_ROWS / ROWS_PER_BLOCK) // 1024
#define NWARPS          (THREADS / 32)            // 4
#define ROWS_PER_WARP   (ROWS_PER_BLOCK / NWARPS) // 32
#define NQUAD           8                         // 8 quads of 4 rows per warp
#define LOOKBACK_W      8                         // aggregates read per round

__device__ float g_aggY[NBLK];
__device__ float g_aggP[NBLK];
__device__ int   g_flag[NBLK];   // generation counter; zero-init at load

// ---------------------------------------------------------------------------
// Fused kernel: software-pipelined dot products (depth-2 prefetch, sustained
//   ~8 LDG.128 in flight per warp) + block scan + decoupled-lookback carry
//   (generation-counter flags, single launch) + single output write.
// ---------------------------------------------------------------------------
__global__ void __launch_bounds__(THREADS, 6)
fused_kernel(const float* __restrict__ x,
             const float* __restrict__ weight,
             const float* __restrict__ weight_h,
             const float* __restrict__ bias,
             float* __restrict__ out)
{
    __shared__ float s_u[ROWS_PER_BLOCK];
    __shared__ float s_wy[NWARPS];
    __shared__ float s_wp[NWARPS];
    __shared__ float s_C;

    const int tid   = threadIdx.x;
    const int wid   = tid >> 5;
    const int lane  = tid & 31;
    const int sub   = lane & 7;    // position within octet
    const int rquad = lane >> 3;   // which of 4 rows in the quad
    const int blk   = blockIdx.x;

    // Generation for this launch (own flag only written by this block; all
    // flags equal between launches; launches serialize on the stream).
    const int genTarget = *((volatile int*)&g_flag[blk]) + 1;

    const float w = weight_h[0];
    const float b = bias[0];

    // Each lane holds the 4 weight chunks its octet-position covers.
    const float4* w4 = reinterpret_cast<const float4*>(weight);
    float4 wc[4];
    #pragma unroll
    for (int i = 0; i < 4; i++) wc[i] = w4[i * 8 + sub];

    const int rowBase = blk * ROWS_PER_BLOCK + wid * ROWS_PER_WARP;

    // Base pointer for this lane's slice of quad q:
    //   row = rowBase + q*4 + rquad, elements [ (i*8+sub)*4 , +4 )
    const float4* laneBase = reinterpret_cast<const float4*>(
        x + (size_t)(rowBase + rquad) * XSTRIDE) + sub;

    // Quad stride in float4 units: 4 rows * 512 floats / 4 = 512 float4
    #define QSTRIDE4 512

    float4 buf[3][4];

    // ---- Prologue: prefetch quads 0 and 1 ----
    #pragma unroll
    for (int i = 0; i < 4; i++) buf[0][i] = __ldcs(laneBase + 0 * QSTRIDE4 + i * 8);
    #pragma unroll
    for (int i = 0; i < 4; i++) buf[1][i] = __ldcs(laneBase + 1 * QSTRIDE4 + i * 8);

    // ---- Pipelined main loop over 8 quads ----
    #pragma unroll
    for (int q = 0; q < NQUAD; q++) {
        if (q + 2 < NQUAD) {
            float4* nb = buf[(q + 2) % 3];
            #pragma unroll
            for (int i = 0; i < 4; i++)
                nb[i] = __ldcs(laneBase + (q + 2) * QSTRIDE4 + i * 8);
        }
        const float4* cb = buf[q % 3];
        float s = 0.0f;
        #pragma unroll
        for (int i = 0; i < 4; i++) {
            s = fmaf(cb[i].x, wc[i].x, s);
            s = fmaf(cb[i].y, wc[i].y, s);
            s = fmaf(cb[i].z, wc[i].z, s);
            s = fmaf(cb[i].w, wc[i].w, s);
        }
        // Octet reduce (3 shfl): result lands on sub==0 of each octet
        s += __shfl_xor_sync(0xFFFFFFFFu, s, 4);
        s += __shfl_xor_sync(0xFFFFFFFFu, s, 2);
        s += __shfl_xor_sync(0xFFFFFFFFu, s, 1);
        if (sub == 0) s_u[wid * ROWS_PER_WARP + q * 4 + rquad] = s + b;
    }
    __syncthreads();

    // ---- Block-local linear-recurrence scan: thread tid owns element tid ----
    const float u = s_u[tid];

    float Y = u, P = w;
    #pragma unroll
    for (int d = 1; d < 32; d <<= 1) {
        const float Yp = __shfl_up_sync(0xFFFFFFFFu, Y, d);
        const float Pp = __shfl_up_sync(0xFFFFFFFFu, P, d);
        if (lane >= d) { Y = fmaf(P, Yp, Y); P *= Pp; }
    }
    if (lane == 31) { s_wy[wid] = Y; s_wp[wid] = P; }
    __syncthreads();

    // Exclusive prefix over earlier warps (serial over <=3 entries)
    float Ew = 0.0f, Pw = 1.0f;
    #pragma unroll
    for (int k = 0; k < NWARPS; k++) {
        if (k < wid) { Ew = fmaf(s_wp[k], Ew, s_wy[k]); Pw *= s_wp[k]; }
    }

    // Block-local inclusive value for this element
    const float yv = fmaf(P, Ew, Y);

    // ---- Publish this block's aggregate (Y_blk, P_blk = w^128) ----
    if (tid == THREADS - 1) {
        g_aggY[blk] = yv;
        g_aggP[blk] = Pw * P;            // w^128
        __threadfence();
        atomicExch(&g_flag[blk], genTarget);
    }

    // ---- w^(tid+1) via binary exponentiation (overlaps lookback wait) ----
    unsigned e = (unsigned)tid + 1u;
    float powv = 1.0f, base = w;
    while (e) {
        if (e & 1u) powv *= base;
        base *= base;
        e >>= 1;
    }

    // ---- Decoupled lookback: compose predecessor aggregates (deterministic,
    //      fixed order; terminates when multiplier hits exact 0) ----
    if (tid == 0) {
        float C = 0.0f;
        if (blk > 0) {
            volatile int*   vf = g_flag;
            volatile float* vy = g_aggY;
            volatile float* vp = g_aggP;
            float M = 1.0f;
            int k = blk - 1;
            while (k >= 0 && M != 0.0f) {
                const int n = (k + 1 < LOOKBACK_W) ? (k + 1) : LOOKBACK_W;
                bool ready;
                do {
                    ready = true;
                    #pragma unroll
                    for (int j = 0; j < LOOKBACK_W; j++)
                        if (j < n && vf[k - j] != genTarget) ready = false;
                } while (!ready);
                float Ys[LOOKBACK_W], Ps[LOOKBACK_W];
                #pragma unroll
                for (int j = 0; j < LOOKBACK_W; j++) {
                    if (j < n) { Ys[j] = vy[k - j]; Ps[j] = vp[k - j]; }
                }
                #pragma unroll
                for (int j = 0; j < LOOKBACK_W; j++) {
                    if (j < n && M != 0.0f) {
                        C = fmaf(M, Ys[j], C);
                        M *= Ps[j];
                    }
                }
                k -= n;
            }
        }
        s_C = C;
    }
    __syncthreads();

    // ---- Final value and single write of the output ----
    const float C = s_C;
    const float fin = fmaf(C, powv, yv);
    out[(size_t)blk * ROWS_PER_BLOCK + tid] = fin;

    if (blk == NBLK - 1 && tid == THREADS - 1) {
        out[B_ROWS]     = fin;   // y_h
        out[B_ROWS + 1] = fin;   // y_h (duplicated output)
    }
}

// ---------------------------------------------------------------------------
extern "C" void kernel_launch(void* const* d_in, const int* in_sizes, int n_in,
                              void* d_out, int out_size)
{
    const float* x        = (const float*)d_in[0];
    const float* weight   = (const float*)d_in[1];
    const float* weight_h = (const float*)d_in[2];
    const float* bias     = (const float*)d_in[3];
    float* out            = (float*)d_out;

    fused_kernel<<<NBLK, THREADS>>>(x, weight, weight_h, bias, out);
}